// round 2
// baseline (speedup 1.0000x reference)
#include <cuda_runtime.h>
#include <math.h>

#define XD 16
#define UD 8
#define AD 32
#define TT 256
#define BB 256

// Persistent scratch (device globals — no allocation at runtime)
__device__ float gA[XD * XD];
__device__ float gZ[XD * XD];
__device__ float gR0[XD * XD];
__device__ float gG[XD * XD];
__device__ float gD[XD * AD];
__device__ float gNxinv[XD];
__device__ float gJ0[XD * XD];
__device__ float gJm[TT * XD * XD];   // prior information matrices, per t
__device__ float gK[TT * XD * AD];    // Kalman gains, per t  (row-major [t][x][a])

__device__ __forceinline__ float softplusf(float x) {
    if (x > 20.f) return x;
    return log1pf(expf(x));
}

// ---------------------------------------------------------------------------
// In-place Gauss-Jordan inverse of a 16x16 SPD matrix, one warp (32 lanes).
// Lane layout: j = lane&15 (column), h = lane>>4; lane owns elements (2m+h, j).
// ---------------------------------------------------------------------------
__device__ __forceinline__ void warp_inv16(float (*E)[17], int lane) {
    const int j = lane & 15, h = lane >> 4;
    for (int k = 0; k < 16; k++) {
        float p = 1.0f / E[k][k];
        float rowk = E[k][j];
        float colk[8];
#pragma unroll
        for (int m = 0; m < 8; m++) colk[m] = E[2 * m + h][k];
        __syncwarp();
#pragma unroll
        for (int m = 0; m < 8; m++) {
            int i = 2 * m + h;
            float val;
            if (i == k) {
                val = (j == k) ? p : rowk * p;
            } else if (j == k) {
                val = -colk[m] * p;
            } else {
                val = E[i][j] - colk[m] * (p * rowk);
            }
            E[i][j] = val;
        }
        __syncwarp();
    }
}

// ---------------------------------------------------------------------------
// Modified Gram-Schmidt QR of a 16x16 matrix; Q has positive-diagonal R
// (matches the reference's Q * sign(diag(R)) convention). X is destroyed.
// ---------------------------------------------------------------------------
__device__ __forceinline__ void warp_qr(float (*X)[17], float (*Q)[17], int lane) {
    const int j = lane & 15, h = lane >> 4;
    for (int k = 0; k < 16; k++) {
        float v = (lane < 16) ? X[lane][k] : 0.f;
        float s = v * v;
#pragma unroll
        for (int off = 8; off >= 1; off >>= 1) s += __shfl_xor_sync(0xffffffffu, s, off);
        float inv = 1.0f / sqrtf(s);
        if (lane < 16) Q[lane][k] = v * inv;
        __syncwarp();
        float dot = 0.f;
        if (lane > k && lane < 16) {
            for (int i = 0; i < 16; i++) dot += Q[i][k] * X[i][lane];
        }
        __syncwarp();
        float dotv = __shfl_sync(0xffffffffu, dot, j);
        if (j > k) {
#pragma unroll
            for (int m = 0; m < 8; m++) {
                int i = 2 * m + h;
                X[i][j] -= dotv * Q[i][k];
            }
        }
        __syncwarp();
    }
}

// ---------------------------------------------------------------------------
// Kernel 0: constants. A from QR(M),QR(N),d; Z, R0, G, D, Nxinv, J0.
// ---------------------------------------------------------------------------
__global__ void prep_kernel(const float* __restrict__ Mmat, const float* __restrict__ Nmat,
                            const float* __restrict__ dvec, const float* __restrict__ Cmat,
                            const float* __restrict__ nx, const float* __restrict__ na,
                            const float* __restrict__ cov0) {
    __shared__ float sX[16][17], sQ[16][17], sU[16][17], sW[16][17], sA[16][17], sE[16][17];
    __shared__ float s1[16], s2[16], nxi[16], nai[32];
    const int lane = threadIdx.x;
    const int j = lane & 15, h = lane >> 4;

    for (int e = lane; e < 256; e += 32) sX[e >> 4][e & 15] = Mmat[e];
    __syncwarp();
    warp_qr(sX, sQ, lane);
    for (int e = lane; e < 256; e += 32) sX[e >> 4][e & 15] = Nmat[e];
    __syncwarp();
    warp_qr(sX, sU, lane);

    if (lane < 16) {
        float dsp = softplusf(dvec[lane]);
        s1[lane] = sqrtf(dsp);
        s2[lane] = 1.0f / sqrtf(1.0f + dsp);
        nxi[lane] = 1.0f / (softplusf(nx[lane]) + 1e-4f);
    }
    nai[lane] = 1.0f / (softplusf(na[lane]) + 1e-4f);
    __syncwarp();

    // W = Uq * diag(s1) * Q
#pragma unroll
    for (int m = 0; m < 8; m++) {
        int i = 2 * m + h;
        float s = 0.f;
        for (int k = 0; k < 16; k++) s += sU[i][k] * s1[k] * sQ[k][j];
        sW[i][j] = s;
    }
    __syncwarp();
    // A = W * diag(s2) * Uq^T
    {
        float Ur[16];
#pragma unroll
        for (int k = 0; k < 16; k++) Ur[k] = sU[j][k] * s2[k];
#pragma unroll
        for (int m = 0; m < 8; m++) {
            int i = 2 * m + h;
            float s = 0.f;
            for (int k = 0; k < 16; k++) s += sW[i][k] * Ur[k];
            sA[i][j] = s;
            gA[i * 16 + j] = s;
        }
    }
    __syncwarp();

    // Z = diag(nxi)*A ;  R0 = A^T diag(nxi) A ;  G = C^T diag(nai) C ;  D = C^T diag(nai)
#pragma unroll
    for (int m = 0; m < 8; m++) {
        int i = 2 * m + h;
        gZ[i * 16 + j] = nxi[i] * sA[i][j];
    }
#pragma unroll
    for (int m = 0; m < 8; m++) {
        int i = 2 * m + h;
        float s = 0.f;
        for (int k = 0; k < 16; k++) s += sA[k][i] * nxi[k] * sA[k][j];
        gR0[i * 16 + j] = s;
    }
#pragma unroll
    for (int m = 0; m < 8; m++) {
        int i = 2 * m + h;
        float s = 0.f;
        for (int k = 0; k < 32; k++) s += Cmat[k * 16 + i] * nai[k] * Cmat[k * 16 + j];
        gG[i * 16 + j] = s;
    }
    for (int e = lane; e < 512; e += 32) {
        int i = e >> 5, c = e & 31;
        gD[i * 32 + c] = Cmat[c * 16 + i] * nai[c];
    }
    if (lane < 16) gNxinv[lane] = nxi[lane];

    // J0 = inv(cov0[0])
    for (int e = lane; e < 256; e += 32) sE[e >> 4][e & 15] = cov0[e];
    __syncwarp();
    warp_inv16(sE, lane);
    for (int e = lane; e < 256; e += 32) gJ0[e] = sE[e >> 4][e & 15];
}

// ---------------------------------------------------------------------------
// Kernel 1: sequential Riccati recursion in information form (1 warp).
//   E = J + R0 ; F = E^{-1} ; Jm = diag(nxi) - Z F Z^T ; J = Jm + G
// ---------------------------------------------------------------------------
__global__ void riccati_kernel() {
    __shared__ float sJ[16][17], sE[16][17], sT[16][17];
    __shared__ float sZ[16][17], sR0[16][17], sG[16][17], sNxi[16];
    const int lane = threadIdx.x;
    const int j = lane & 15, h = lane >> 4;

    for (int e = lane; e < 256; e += 32) {
        int i = e >> 4, c = e & 15;
        sJ[i][c] = gJ0[e];
        sZ[i][c] = gZ[e];
        sR0[i][c] = gR0[e];
        sG[i][c] = gG[e];
    }
    if (lane < 16) sNxi[lane] = gNxinv[lane];
    __syncwarp();

    float Zr[16];  // row j of Z, constant over t
#pragma unroll
    for (int k = 0; k < 16; k++) Zr[k] = sZ[j][k];

    for (int t = 0; t < TT; t++) {
#pragma unroll
        for (int m = 0; m < 8; m++) {
            int i = 2 * m + h;
            sE[i][j] = sJ[i][j] + sR0[i][j];
        }
        __syncwarp();
        warp_inv16(sE, lane);
        // T = Z * F   (F = sE)
        float Fc[16];
#pragma unroll
        for (int k = 0; k < 16; k++) Fc[k] = sE[k][j];
#pragma unroll
        for (int m = 0; m < 8; m++) {
            int i = 2 * m + h;
            float s = 0.f;
#pragma unroll
            for (int k = 0; k < 16; k++) s += sZ[i][k] * Fc[k];
            sT[i][j] = s;
        }
        __syncwarp();
        // Jm = diag(nxi) - T * Z^T  ;  J = Jm + G
        float* gout = gJm + t * 256;
#pragma unroll
        for (int m = 0; m < 8; m++) {
            int i = 2 * m + h;
            float s = (i == j) ? sNxi[i] : 0.f;
#pragma unroll
            for (int k = 0; k < 16; k++) s -= sT[i][k] * Zr[k];
            gout[i * 16 + j] = s;
            sJ[i][j] = s + sG[i][j];
        }
        __syncwarp();
    }
}

// ---------------------------------------------------------------------------
// Kernel 2: parallel over t — P+ = (Jm + G)^{-1},  K_t = P+ * D
// ---------------------------------------------------------------------------
__global__ void gains_kernel() {
    __shared__ float sE[16][17];
    __shared__ float sD[16][33];
    const int t = blockIdx.x;
    const int lane = threadIdx.x;
    for (int e = lane; e < 512; e += 32) sD[e >> 5][e & 31] = gD[e];
    for (int e = lane; e < 256; e += 32) sE[e >> 4][e & 15] = gJm[t * 256 + e] + gG[e];
    __syncwarp();
    warp_inv16(sE, lane);
    float* kout = gK + t * (XD * AD);
#pragma unroll
    for (int r = 0; r < 16; r++) {
        float s = 0.f;
#pragma unroll
        for (int m = 0; m < 16; m++) s += sE[r][m] * sD[m][lane];
        kout[r * 32 + lane] = s;
    }
}

// ---------------------------------------------------------------------------
// Kernel 3: per-batch mean recursion (256 blocks x 1 warp).
//   nm = A*mean + B*u_t ; inn = a_t - C*nm ; mean = nm + K_t*inn
// ---------------------------------------------------------------------------
__global__ void __launch_bounds__(32) means_kernel(
    const float* __restrict__ mean0, const float* __restrict__ u,
    const float* __restrict__ a, const float* __restrict__ Bmat,
    const float* __restrict__ Cmat, float* __restrict__ out) {
    __shared__ float sA[16][17], sB[16][9], sC[32][17];
    __shared__ float sMean[16], sNM[16], sInn[32];
    const int b = blockIdx.x;
    const int lane = threadIdx.x;

    for (int e = lane; e < 256; e += 32) sA[e >> 4][e & 15] = gA[e];
    for (int e = lane; e < 128; e += 32) sB[e >> 3][e & 7] = Bmat[e];
    for (int e = lane; e < 512; e += 32) sC[e >> 4][e & 15] = Cmat[e];
    if (lane < 16) sMean[lane] = mean0[b * 16 + lane];
    __syncwarp();

    const float* ub = u + (size_t)b * TT * UD;
    const float* ab = a + (size_t)b * TT * AD;
    float* ob = out + (size_t)b * TT * XD;

    float4 kf[8];
    if (lane < 16) {
        const float4* kp = reinterpret_cast<const float4*>(gK + lane * 32);
#pragma unroll
        for (int q = 0; q < 8; q++) kf[q] = kp[q];
    }

    for (int t = 0; t < TT; t++) {
        float4 ua = *reinterpret_cast<const float4*>(ub + t * 8);
        float4 ub4 = *reinterpret_cast<const float4*>(ub + t * 8 + 4);
        float nm = 0.f;
        if (lane < 16) {
#pragma unroll
            for (int k = 0; k < 16; k++) nm += sA[lane][k] * sMean[k];
            nm += sB[lane][0] * ua.x + sB[lane][1] * ua.y + sB[lane][2] * ua.z +
                  sB[lane][3] * ua.w + sB[lane][4] * ub4.x + sB[lane][5] * ub4.y +
                  sB[lane][6] * ub4.z + sB[lane][7] * ub4.w;
            sNM[lane] = nm;
        }
        __syncwarp();
        {
            float inn = ab[t * 32 + lane];
#pragma unroll
            for (int k = 0; k < 16; k++) inn -= sC[lane][k] * sNM[k];
            sInn[lane] = inn;
        }
        __syncwarp();
        if (lane < 16) {
            float m = nm;
#pragma unroll
            for (int q = 0; q < 8; q++) {
                m += kf[q].x * sInn[4 * q + 0] + kf[q].y * sInn[4 * q + 1] +
                     kf[q].z * sInn[4 * q + 2] + kf[q].w * sInn[4 * q + 3];
            }
            sMean[lane] = m;
            ob[t * 16 + lane] = m;
            // software-pipelined prefetch of next K_t
            int tn = (t + 1 < TT) ? (t + 1) : t;
            const float4* kn = reinterpret_cast<const float4*>(gK + tn * (XD * AD) + lane * 32);
#pragma unroll
            for (int q = 0; q < 8; q++) kf[q] = kn[q];
        }
        __syncwarp();
    }
}

// ---------------------------------------------------------------------------
extern "C" void kernel_launch(void* const* d_in, const int* in_sizes, int n_in,
                              void* d_out, int out_size) {
    const float* mean0 = (const float*)d_in[0];
    const float* cov0  = (const float*)d_in[1];
    const float* u     = (const float*)d_in[2];
    const float* a     = (const float*)d_in[3];
    const float* Mmat  = (const float*)d_in[4];
    const float* Nmat  = (const float*)d_in[5];
    const float* dvec  = (const float*)d_in[6];
    const float* Bmat  = (const float*)d_in[7];
    const float* Cmat  = (const float*)d_in[8];
    const float* nx    = (const float*)d_in[9];
    const float* na    = (const float*)d_in[10];
    float* out = (float*)d_out;

    prep_kernel<<<1, 32>>>(Mmat, Nmat, dvec, Cmat, nx, na, cov0);
    riccati_kernel<<<1, 32>>>();
    gains_kernel<<<TT, 32>>>();
    means_kernel<<<BB, 32>>>(mean0, u, a, Bmat, Cmat, out);
}

// round 3
// speedup vs baseline: 3.5902x; 3.5902x over previous
#include <cuda_runtime.h>
#include <math.h>

#define XD 16
#define UD 8
#define AD 32
#define TT 256
#define BB 256
#define T0 96          // Riccati steps computed exactly; converged afterwards
#define CH 16          // time-chunk for means kernel

// Persistent scratch (device globals — no runtime allocation)
__device__ float gA[XD * XD];
__device__ float gZ[XD * XD];
__device__ float gR0[XD * XD];
__device__ float gG[XD * XD];
__device__ float gD[XD * AD];
__device__ float gCA[AD * XD];
__device__ float gCB[AD * UD];
__device__ float gNxinv[XD];
__device__ float gJ0[XD * XD];
__device__ float gJ[TT * XD * XD];     // posterior information matrices (t < T0 written)
__device__ float gK[TT * XD * AD];     // Kalman gains [t][x][a]
__device__ float gMT[TT * XD * XD];    // M_t^T : gMT[t][k][i] = M_t[i][k]
__device__ float gW[TT * XD * UD];     // W_t = (I-KC)B  [t][x][u]
__device__ float gV[(size_t)BB * TT * XD]; // v_{b,t} = W_t u + K_t a

__device__ __forceinline__ float softplusf(float x) {
    if (x > 20.f) return x;
    return log1pf(expf(x));
}

// ---------------------------------------------------------------------------
// Shared-memory Gauss-Jordan inverse of 16x16 SPD (one warp). Used in the
// PARALLEL kernels (prep, gains) where latency is hidden across blocks.
// ---------------------------------------------------------------------------
__device__ __forceinline__ void warp_inv16(float (*E)[17], int lane) {
    const int j = lane & 15, h = lane >> 4;
    for (int k = 0; k < 16; k++) {
        float p = 1.0f / E[k][k];
        float rowk = E[k][j];
        float colk[8];
#pragma unroll
        for (int m = 0; m < 8; m++) colk[m] = E[2 * m + h][k];
        __syncwarp();
#pragma unroll
        for (int m = 0; m < 8; m++) {
            int i = 2 * m + h;
            float val;
            if (i == k) {
                val = (j == k) ? p : rowk * p;
            } else if (j == k) {
                val = -colk[m] * p;
            } else {
                val = E[i][j] - colk[m] * (p * rowk);
            }
            E[i][j] = val;
        }
        __syncwarp();
    }
}

// MGS QR with positive-diagonal R convention (matches reference sign fix)
__device__ __forceinline__ void warp_qr(float (*X)[17], float (*Q)[17], int lane) {
    const int j = lane & 15, h = lane >> 4;
    for (int k = 0; k < 16; k++) {
        float v = (lane < 16) ? X[lane][k] : 0.f;
        float s = v * v;
#pragma unroll
        for (int off = 8; off >= 1; off >>= 1) s += __shfl_xor_sync(0xffffffffu, s, off);
        float inv = 1.0f / sqrtf(s);
        if (lane < 16) Q[lane][k] = v * inv;
        __syncwarp();
        float dot = 0.f;
        if (lane > k && lane < 16) {
            for (int i = 0; i < 16; i++) dot += Q[i][k] * X[i][lane];
        }
        __syncwarp();
        float dotv = __shfl_sync(0xffffffffu, dot, j);
        if (j > k) {
#pragma unroll
            for (int m = 0; m < 8; m++) {
                int i = 2 * m + h;
                X[i][j] -= dotv * Q[i][k];
            }
        }
        __syncwarp();
    }
}

// ---------------------------------------------------------------------------
// Kernel 0: constants
// ---------------------------------------------------------------------------
__global__ void prep_kernel(const float* __restrict__ Mmat, const float* __restrict__ Nmat,
                            const float* __restrict__ dvec, const float* __restrict__ Bmat,
                            const float* __restrict__ Cmat,
                            const float* __restrict__ nx, const float* __restrict__ na,
                            const float* __restrict__ cov0) {
    __shared__ float sX[16][17], sQ[16][17], sU[16][17], sW[16][17], sA[16][17], sE[16][17];
    __shared__ float s1[16], s2[16], nxi[16], nai[32];
    const int lane = threadIdx.x;
    const int j = lane & 15, h = lane >> 4;

    for (int e = lane; e < 256; e += 32) sX[e >> 4][e & 15] = Mmat[e];
    __syncwarp();
    warp_qr(sX, sQ, lane);
    for (int e = lane; e < 256; e += 32) sX[e >> 4][e & 15] = Nmat[e];
    __syncwarp();
    warp_qr(sX, sU, lane);

    if (lane < 16) {
        float dsp = softplusf(dvec[lane]);
        s1[lane] = sqrtf(dsp);
        s2[lane] = 1.0f / sqrtf(1.0f + dsp);
        nxi[lane] = 1.0f / (softplusf(nx[lane]) + 1e-4f);
    }
    nai[lane] = 1.0f / (softplusf(na[lane]) + 1e-4f);
    __syncwarp();

    // W = Uq diag(s1) Q ; A = W diag(s2) Uq^T
#pragma unroll
    for (int m = 0; m < 8; m++) {
        int i = 2 * m + h;
        float s = 0.f;
        for (int k = 0; k < 16; k++) s += sU[i][k] * s1[k] * sQ[k][j];
        sW[i][j] = s;
    }
    __syncwarp();
    {
        float Ur[16];
#pragma unroll
        for (int k = 0; k < 16; k++) Ur[k] = sU[j][k] * s2[k];
#pragma unroll
        for (int m = 0; m < 8; m++) {
            int i = 2 * m + h;
            float s = 0.f;
            for (int k = 0; k < 16; k++) s += sW[i][k] * Ur[k];
            sA[i][j] = s;
            gA[i * 16 + j] = s;
        }
    }
    __syncwarp();

    // Z, R0, G, D, Nxinv
#pragma unroll
    for (int m = 0; m < 8; m++) {
        int i = 2 * m + h;
        gZ[i * 16 + j] = nxi[i] * sA[i][j];
    }
#pragma unroll
    for (int m = 0; m < 8; m++) {
        int i = 2 * m + h;
        float s = 0.f;
        for (int k = 0; k < 16; k++) s += sA[k][i] * nxi[k] * sA[k][j];
        gR0[i * 16 + j] = s;
    }
#pragma unroll
    for (int m = 0; m < 8; m++) {
        int i = 2 * m + h;
        float s = 0.f;
        for (int k = 0; k < 32; k++) s += Cmat[k * 16 + i] * nai[k] * Cmat[k * 16 + j];
        gG[i * 16 + j] = s;
    }
    for (int e = lane; e < 512; e += 32) {
        int i = e >> 5, c = e & 31;
        gD[i * 32 + c] = Cmat[c * 16 + i] * nai[c];
    }
    if (lane < 16) gNxinv[lane] = nxi[lane];

    // CA = C*A (32x16), CB = C*B (32x8) — lane = C row
    {
        float Crow[16];
#pragma unroll
        for (int k = 0; k < 16; k++) Crow[k] = Cmat[lane * 16 + k];
#pragma unroll
        for (int jj = 0; jj < 16; jj++) {
            float s = 0.f;
#pragma unroll
            for (int k = 0; k < 16; k++) s += Crow[k] * sA[k][jj];
            gCA[lane * 16 + jj] = s;
        }
#pragma unroll
        for (int jj = 0; jj < 8; jj++) {
            float s = 0.f;
#pragma unroll
            for (int k = 0; k < 16; k++) s += Crow[k] * Bmat[k * 8 + jj];
            gCB[lane * 8 + jj] = s;
        }
    }

    // J0 = inv(cov0[0])
    for (int e = lane; e < 256; e += 32) sE[e >> 4][e & 15] = cov0[e];
    __syncwarp();
    warp_inv16(sE, lane);
    for (int e = lane; e < 256; e += 32) gJ0[e] = sE[e >> 4][e & 15];
}

// ---------------------------------------------------------------------------
// Kernel 1: sequential Riccati (T0 steps), pure registers + shfl, one warp.
// Layout: lane = j + 16*h ; lane owns col j, rows h*8..h*8+7 (reg index m).
//   E = J + R0 ; F = E^{-1} ; Jm = diag(nxi) - Z F Z^T ; J = Jm + G (stored)
// ---------------------------------------------------------------------------
__global__ void __launch_bounds__(32) riccati_kernel() {
    __shared__ float sZ[16][17];
    const unsigned FULL = 0xffffffffu;
    const int lane = threadIdx.x;
    const int j = lane & 15;
    const int h = lane >> 4;

    float Rc[8], Gc[8], J[8], Zr[16];
#pragma unroll
    for (int m = 0; m < 8; m++) {
        int i = (h << 3) + m;
        Rc[m] = gR0[i * 16 + j];
        Gc[m] = gG[i * 16 + j];
        J[m]  = gJ0[i * 16 + j];
    }
#pragma unroll
    for (int k = 0; k < 16; k++) Zr[k] = gZ[j * 16 + k];
    for (int e = lane; e < 256; e += 32) sZ[e >> 4][e & 15] = gZ[e];
    float nxi = gNxinv[j];
    __syncwarp();

    for (int t = 0; t < T0; t++) {
        float E[8];
#pragma unroll
        for (int m = 0; m < 8; m++) E[m] = J[m] + Rc[m];

        // --- in-register Gauss-Jordan inverse ---
#pragma unroll
        for (int k = 0; k < 16; k++) {
            const int hk = k >> 3;           // half holding row k
            const int rk = k & 7;            // register index of row k
            float piv = __shfl_sync(FULL, E[rk], k + (hk << 4));
            float p = 1.0f / piv;
            float rowk = __shfl_sync(FULL, E[rk], j + (hk << 4));
            float colk[8];
#pragma unroll
            for (int m = 0; m < 8; m++) colk[m] = __shfl_sync(FULL, E[m], k + (h << 4));
            float pr = p * rowk;
#pragma unroll
            for (int m = 0; m < 8; m++) {
                int i = (h << 3) + m;
                float En = E[m] - colk[m] * pr;
                if (i == k) En = (j == k) ? p : pr;
                else if (j == k) En = -colk[m] * p;
                E[m] = En;
            }
        }

        // gather full column j of F
        float Fc[16];
#pragma unroll
        for (int m = 0; m < 8; m++) {
            Fc[(h << 3) + m] = E[m];
            Fc[((1 - h) << 3) + m] = __shfl_xor_sync(FULL, E[m], 16);
        }

        // T[:,j] (my rows): T[i][j] = sum_k Z[i][k] * F[k][j]
        float Tc[8];
#pragma unroll
        for (int m = 0; m < 8; m++) {
            int i = (h << 3) + m;
            float s = 0.f;
#pragma unroll
            for (int k = 0; k < 16; k++) s += sZ[i][k] * Fc[k];
            Tc[m] = s;
        }

        // Jm[i][j] = -sum_k T[i][k] * Z[j][k]   (T[i][k] lives in lane k+16*h, reg m)
        float acc[8];
#pragma unroll
        for (int m = 0; m < 8; m++) acc[m] = 0.f;
#pragma unroll
        for (int k = 0; k < 16; k++) {
            float zk = Zr[k];
#pragma unroll
            for (int m = 0; m < 8; m++)
                acc[m] -= __shfl_sync(FULL, Tc[m], k + (h << 4)) * zk;
        }

        float* gj = gJ + t * 256;
#pragma unroll
        for (int m = 0; m < 8; m++) {
            int i = (h << 3) + m;
            float jm = acc[m] + ((i == j) ? nxi : 0.f);
            float jn = jm + Gc[m];
            gj[i * 16 + j] = jn;
            J[m] = jn;
        }
    }
}

// ---------------------------------------------------------------------------
// Kernel 2: parallel over t — P+ = gJ[min(t,T0-1)]^{-1}, K_t = P+ D,
//           M_t = A - K_t*CA (stored transposed), W_t = B - K_t*CB
// ---------------------------------------------------------------------------
__global__ void __launch_bounds__(32) gains_kernel(const float* __restrict__ Bmat) {
    __shared__ float sE[16][17], sD[16][33], sK[16][33], sA[16][17];
    __shared__ float sCA[32][17], sCB[32][9];
    const int t = blockIdx.x;
    const int ts = (t < T0) ? t : (T0 - 1);
    const int lane = threadIdx.x;
    const int j = lane & 15, h = lane >> 4;

    for (int e = lane; e < 512; e += 32) sD[e >> 5][e & 31] = gD[e];
    for (int e = lane; e < 256; e += 32) sE[e >> 4][e & 15] = gJ[ts * 256 + e];
    for (int e = lane; e < 256; e += 32) sA[e >> 4][e & 15] = gA[e];
    for (int e = lane; e < 512; e += 32) sCA[e >> 4][e & 15] = gCA[e];
    for (int e = lane; e < 256; e += 32) sCB[e >> 3][e & 7] = gCB[e];
    __syncwarp();
    warp_inv16(sE, lane);

    float* kout = gK + t * (XD * AD);
#pragma unroll
    for (int r = 0; r < 16; r++) {
        float s = 0.f;
#pragma unroll
        for (int m = 0; m < 16; m++) s += sE[r][m] * sD[m][lane];
        kout[r * 32 + lane] = s;
        sK[r][lane] = s;
    }
    __syncwarp();

    // M col j (rows h*8+m): M[i][j] = A[i][j] - sum_l K[i][l]*CA[l][j]
    float* mt = gMT + t * 256;
#pragma unroll
    for (int m = 0; m < 8; m++) {
        int i = (h << 3) + m;
        float s = sA[i][j];
#pragma unroll
        for (int l = 0; l < 32; l++) s -= sK[i][l] * sCA[l][j];
        mt[j * 16 + i] = s;   // transposed store
    }
    // W: 128 elems
    float* wt = gW + t * 128;
    for (int e = lane; e < 128; e += 32) {
        int i = e >> 3, jw = e & 7;
        float s = Bmat[i * 8 + jw];
#pragma unroll
        for (int l = 0; l < 32; l++) s -= sK[i][l] * sCB[l][jw];
        wt[i * 8 + jw] = s;
    }
}

// ---------------------------------------------------------------------------
// Kernel 3: v_{b,t} = W_t u_{b,t} + K_t a_{b,t}  — fully parallel (t-blocks, b-threads)
// ---------------------------------------------------------------------------
__global__ void __launch_bounds__(256) vcomp_kernel(const float* __restrict__ u,
                                                    const float* __restrict__ a) {
    __shared__ float sK[16][32];
    __shared__ float sW[16][8];
    const int t = blockIdx.x;
    const int b = threadIdx.x;
    for (int e = threadIdx.x; e < 512; e += 256) ((float*)sK)[e] = gK[t * 512 + e];
    for (int e = threadIdx.x; e < 128; e += 256) ((float*)sW)[e] = gW[t * 128 + e];
    __syncthreads();

    const float4* up = reinterpret_cast<const float4*>(u + ((size_t)b * TT + t) * 8);
    const float4* ap = reinterpret_cast<const float4*>(a + ((size_t)b * TT + t) * 32);
    float uu[8], aa[32];
    float4 v0 = up[0], v1 = up[1];
    uu[0]=v0.x; uu[1]=v0.y; uu[2]=v0.z; uu[3]=v0.w;
    uu[4]=v1.x; uu[5]=v1.y; uu[6]=v1.z; uu[7]=v1.w;
#pragma unroll
    for (int q = 0; q < 8; q++) {
        float4 av = ap[q];
        aa[4*q]=av.x; aa[4*q+1]=av.y; aa[4*q+2]=av.z; aa[4*q+3]=av.w;
    }
    float* vp = gV + ((size_t)b * TT + t) * 16;
#pragma unroll
    for (int i = 0; i < 16; i++) {
        float s = 0.f;
#pragma unroll
        for (int k = 0; k < 8; k++) s += sW[i][k] * uu[k];
#pragma unroll
        for (int l = 0; l < 32; l++) s += sK[i][l] * aa[l];
        vp[i] = s;
    }
}

// ---------------------------------------------------------------------------
// Kernel 4: mean recurrence.  mean_t = M_t mean_{t-1} + v_{b,t}
// 32 blocks x 8 warps; warp = one batch; M^T chunks + v staged in shared.
// ---------------------------------------------------------------------------
__global__ void __launch_bounds__(256) means_kernel(const float* __restrict__ mean0,
                                                    float* __restrict__ out) {
    __shared__ float sMT[CH * 256];      // 16 KB
    __shared__ float sV[8 * CH * 16];    // 8 KB
    const unsigned FULL = 0xffffffffu;
    const int w = threadIdx.x >> 5;
    const int lane = threadIdx.x & 31;
    const int i = lane & 15;
    const int b = blockIdx.x * 8 + w;

    float mean = mean0[b * 16 + i];
    float* ob = out + (size_t)b * TT * 16;

    for (int c = 0; c < TT / CH; c++) {
        __syncthreads();
        for (int e = threadIdx.x; e < CH * 256; e += 256)
            sMT[e] = gMT[c * (CH * 256) + e];
        for (int e = threadIdx.x; e < 8 * CH * 16; e += 256) {
            int wb = e >> 8;          // CH*16 == 256
            int r = e & 255;
            sV[e] = gV[((size_t)(blockIdx.x * 8 + wb) * TT + c * CH) * 16 + r];
        }
        __syncthreads();

#pragma unroll 4
        for (int tt = 0; tt < CH; tt++) {
            float acc = sV[(w * CH + tt) * 16 + i];
            const float* Mp = &sMT[tt * 256];
#pragma unroll
            for (int k = 0; k < 16; k++)
                acc += Mp[k * 16 + i] * __shfl_sync(FULL, mean, k, 16);
            mean = acc;
            if (lane < 16) ob[(c * CH + tt) * 16 + i] = acc;
        }
    }
}

// ---------------------------------------------------------------------------
extern "C" void kernel_launch(void* const* d_in, const int* in_sizes, int n_in,
                              void* d_out, int out_size) {
    const float* mean0 = (const float*)d_in[0];
    const float* cov0  = (const float*)d_in[1];
    const float* u     = (const float*)d_in[2];
    const float* a     = (const float*)d_in[3];
    const float* Mmat  = (const float*)d_in[4];
    const float* Nmat  = (const float*)d_in[5];
    const float* dvec  = (const float*)d_in[6];
    const float* Bmat  = (const float*)d_in[7];
    const float* Cmat  = (const float*)d_in[8];
    const float* nx    = (const float*)d_in[9];
    const float* na    = (const float*)d_in[10];
    float* out = (float*)d_out;

    prep_kernel<<<1, 32>>>(Mmat, Nmat, dvec, Bmat, Cmat, nx, na, cov0);
    riccati_kernel<<<1, 32>>>();
    gains_kernel<<<TT, 32>>>(Bmat);
    vcomp_kernel<<<TT, 256>>>(u, a);
    means_kernel<<<BB / 8, 256>>>(mean0, out);
}

// round 4
// speedup vs baseline: 6.7787x; 1.8881x over previous
#include <cuda_runtime.h>
#include <math.h>

#define XD 16
#define UD 8
#define AD 32
#define TT 256
#define BB 256
#define T0 32          // Riccati steps computed exactly; converged afterwards
#define CH 16          // time-chunk for means kernel

// Persistent scratch (device globals — no runtime allocation)
__device__ float gA[XD * XD];
__device__ float gZ[XD * XD];
__device__ float gR0[XD * XD];
__device__ float gG[XD * XD];
__device__ float gD[XD * AD];
__device__ float gCA[AD * XD];
__device__ float gCB[AD * UD];
__device__ float gNxinv[XD];
__device__ float gJ0[XD * XD];
__device__ float gJ[T0 * XD * XD];         // posterior information matrices
__device__ float gMT[TT * XD * XD];        // M_t^T : gMT[t][j][i] = M_t[i][j]
__device__ float gV[(size_t)TT * BB * XD]; // v layout [t][b][16]

__device__ __forceinline__ float softplusf(float x) {
    if (x > 20.f) return x;
    return log1pf(expf(x));
}

// ---------------------------------------------------------------------------
// Shared-memory Gauss-Jordan inverse of 16x16 SPD (one warp).
// ---------------------------------------------------------------------------
__device__ __forceinline__ void warp_inv16(float (*E)[17], int lane) {
    const int j = lane & 15, h = lane >> 4;
    for (int k = 0; k < 16; k++) {
        float p = 1.0f / E[k][k];
        float rowk = E[k][j];
        float colk[8];
#pragma unroll
        for (int m = 0; m < 8; m++) colk[m] = E[2 * m + h][k];
        __syncwarp();
#pragma unroll
        for (int m = 0; m < 8; m++) {
            int i = 2 * m + h;
            float val;
            if (i == k) {
                val = (j == k) ? p : rowk * p;
            } else if (j == k) {
                val = -colk[m] * p;
            } else {
                val = E[i][j] - colk[m] * (p * rowk);
            }
            E[i][j] = val;
        }
        __syncwarp();
    }
}

// MGS QR with positive-diagonal R convention (matches reference sign fix)
__device__ __forceinline__ void warp_qr(float (*X)[17], float (*Q)[17], int lane) {
    const int j = lane & 15, h = lane >> 4;
    for (int k = 0; k < 16; k++) {
        float v = (lane < 16) ? X[lane][k] : 0.f;
        float s = v * v;
#pragma unroll
        for (int off = 8; off >= 1; off >>= 1) s += __shfl_xor_sync(0xffffffffu, s, off);
        float inv = 1.0f / sqrtf(s);
        if (lane < 16) Q[lane][k] = v * inv;
        __syncwarp();
        float dot = 0.f;
        if (lane > k && lane < 16) {
            for (int i = 0; i < 16; i++) dot += Q[i][k] * X[i][lane];
        }
        __syncwarp();
        float dotv = __shfl_sync(0xffffffffu, dot, j);
        if (j > k) {
#pragma unroll
            for (int m = 0; m < 8; m++) {
                int i = 2 * m + h;
                X[i][j] -= dotv * Q[i][k];
            }
        }
        __syncwarp();
    }
}

// ---------------------------------------------------------------------------
// Kernel 0: prep (constants) + sequential Riccati, one warp, one launch.
// ---------------------------------------------------------------------------
__global__ void __launch_bounds__(32) prep_riccati_kernel(
    const float* __restrict__ Mmat, const float* __restrict__ Nmat,
    const float* __restrict__ dvec, const float* __restrict__ Bmat,
    const float* __restrict__ Cmat,
    const float* __restrict__ nx, const float* __restrict__ na,
    const float* __restrict__ cov0) {
    __shared__ float sX[16][17], sQ[16][17], sU[16][17], sW[16][17], sA[16][17], sE[16][17];
    __shared__ float sZ[16][17], sT[16][17];
    __shared__ float s1[16], s2[16], nxi[16], nai[32];
    const unsigned FULL = 0xffffffffu;
    const int lane = threadIdx.x;
    const int j = lane & 15, h = lane >> 4;

    // ---------- prep ----------
    for (int e = lane; e < 256; e += 32) sX[e >> 4][e & 15] = Mmat[e];
    __syncwarp();
    warp_qr(sX, sQ, lane);
    for (int e = lane; e < 256; e += 32) sX[e >> 4][e & 15] = Nmat[e];
    __syncwarp();
    warp_qr(sX, sU, lane);

    if (lane < 16) {
        float dsp = softplusf(dvec[lane]);
        s1[lane] = sqrtf(dsp);
        s2[lane] = 1.0f / sqrtf(1.0f + dsp);
        nxi[lane] = 1.0f / (softplusf(nx[lane]) + 1e-4f);
    }
    nai[lane] = 1.0f / (softplusf(na[lane]) + 1e-4f);
    __syncwarp();

    // W = Uq diag(s1) Q ; A = W diag(s2) Uq^T
#pragma unroll
    for (int m = 0; m < 8; m++) {
        int i = 2 * m + h;
        float s = 0.f;
        for (int k = 0; k < 16; k++) s += sU[i][k] * s1[k] * sQ[k][j];
        sW[i][j] = s;
    }
    __syncwarp();
    {
        float Ur[16];
#pragma unroll
        for (int k = 0; k < 16; k++) Ur[k] = sU[j][k] * s2[k];
#pragma unroll
        for (int m = 0; m < 8; m++) {
            int i = 2 * m + h;
            float s = 0.f;
            for (int k = 0; k < 16; k++) s += sW[i][k] * Ur[k];
            sA[i][j] = s;
            gA[i * 16 + j] = s;
        }
    }
    __syncwarp();

    // sZ = diag(nxi)*A (kept in shared for riccati); R0, G, D to globals
#pragma unroll
    for (int m = 0; m < 8; m++) {
        int i = 2 * m + h;
        float z = nxi[i] * sA[i][j];
        sZ[i][j] = z;
        gZ[i * 16 + j] = z;
    }
    float Rc[8], Gc[8], Jr[8];
#pragma unroll
    for (int m = 0; m < 8; m++) {
        int i = 2 * m + h;
        float s = 0.f;
        for (int k = 0; k < 16; k++) s += sA[k][i] * nxi[k] * sA[k][j];
        gR0[i * 16 + j] = s;
        // reuse for riccati below (note: riccati layout differs; reload later)
    }
#pragma unroll
    for (int m = 0; m < 8; m++) {
        int i = 2 * m + h;
        float s = 0.f;
        for (int k = 0; k < 32; k++) s += Cmat[k * 16 + i] * nai[k] * Cmat[k * 16 + j];
        gG[i * 16 + j] = s;
    }
    for (int e = lane; e < 512; e += 32) {
        int i = e >> 5, c = e & 31;
        gD[i * 32 + c] = Cmat[c * 16 + i] * nai[c];
    }
    if (lane < 16) gNxinv[lane] = nxi[lane];

    // CA = C*A (32x16), CB = C*B (32x8) — lane = C row
    {
        float Crow[16];
#pragma unroll
        for (int k = 0; k < 16; k++) Crow[k] = Cmat[lane * 16 + k];
#pragma unroll
        for (int jj = 0; jj < 16; jj++) {
            float s = 0.f;
#pragma unroll
            for (int k = 0; k < 16; k++) s += Crow[k] * sA[k][jj];
            gCA[lane * 16 + jj] = s;
        }
#pragma unroll
        for (int jj = 0; jj < 8; jj++) {
            float s = 0.f;
#pragma unroll
            for (int k = 0; k < 16; k++) s += Crow[k] * Bmat[k * 8 + jj];
            gCB[lane * 8 + jj] = s;
        }
    }

    // J0 = inv(cov0[0])
    for (int e = lane; e < 256; e += 32) sE[e >> 4][e & 15] = cov0[e];
    __syncwarp();
    warp_inv16(sE, lane);

    __threadfence_block();
    __syncwarp();

    // ---------- riccati (layout: lane = j + 16*h owns col j, rows h*8..h*8+7) ----------
#pragma unroll
    for (int m = 0; m < 8; m++) {
        int i = (h << 3) + m;
        Rc[m] = gR0[i * 16 + j];
        Gc[m] = gG[i * 16 + j];
        Jr[m] = sE[i][j];          // J0
    }
    float Zr[16];
#pragma unroll
    for (int k = 0; k < 16; k++) Zr[k] = sZ[j][k];
    float nxij = nxi[j];
    __syncwarp();

    for (int t = 0; t < T0; t++) {
        float E[8];
#pragma unroll
        for (int m = 0; m < 8; m++) E[m] = Jr[m] + Rc[m];

        // in-register Gauss-Jordan inverse
#pragma unroll
        for (int k = 0; k < 16; k++) {
            const int hk = k >> 3;
            const int rk = k & 7;
            float piv = __shfl_sync(FULL, E[rk], k + (hk << 4));
            float p = 1.0f / piv;
            float rowk = __shfl_sync(FULL, E[rk], j + (hk << 4));
            float colk[8];
#pragma unroll
            for (int m = 0; m < 8; m++) colk[m] = __shfl_sync(FULL, E[m], k + (h << 4));
            float pr = p * rowk;
#pragma unroll
            for (int m = 0; m < 8; m++) {
                int i = (h << 3) + m;
                float En = E[m] - colk[m] * pr;
                if (i == k) En = (j == k) ? p : pr;
                else if (j == k) En = -colk[m] * p;
                E[m] = En;
            }
        }

        // full column j of F
        float Fc[16];
#pragma unroll
        for (int m = 0; m < 8; m++) {
            Fc[(h << 3) + m] = E[m];
            Fc[((1 - h) << 3) + m] = __shfl_xor_sync(FULL, E[m], 16);
        }

        // T[:,j]: T[i][j] = sum_k Z[i][k] F[k][j]  -> store to shared
#pragma unroll
        for (int m = 0; m < 8; m++) {
            int i = (h << 3) + m;
            float s = 0.f;
#pragma unroll
            for (int k = 0; k < 16; k++) s += sZ[i][k] * Fc[k];
            sT[i][j] = s;
        }
        __syncwarp();

        // Jm[i][j] = nxi_ij - sum_k T[i][k] Z[j][k] ; J = Jm + G (stored)
        float* gj = gJ + t * 256;
#pragma unroll
        for (int m = 0; m < 8; m++) {
            int i = (h << 3) + m;
            float s = (i == j) ? nxij : 0.f;
#pragma unroll
            for (int k = 0; k < 16; k++) s -= sT[i][k] * Zr[k];
            float jn = s + Gc[m];
            gj[i * 16 + j] = jn;
            Jr[m] = jn;
        }
        __syncwarp();
    }
}

// ---------------------------------------------------------------------------
// Kernel 1: per-t (256 blocks x 256 threads), fused gains + v.
//   warp0: P+ = gJ[min(t,T0-1)]^{-1}, K = P+ D   (warps 1-7 stage a-tile)
//   all:   M_t = A - K CA (-> gMT, transposed), W_t = B - K CB
//   all:   v_{b,t} = W_t u + K a   (thread = b), gV layout [t][b][16]
// ---------------------------------------------------------------------------
__global__ void __launch_bounds__(256) gainsv_kernel(const float* __restrict__ Bmat,
                                                     const float* __restrict__ u,
                                                     const float* __restrict__ a) {
    __shared__ float sE[16][17], sD[16][33], sK[16][33], sA[16][17];
    __shared__ float sCA[32][17], sCB[32][9], sW[16][9];
    __shared__ float sa[256 * 33];
    const int t = blockIdx.x;
    const int ts = (t < T0) ? t : (T0 - 1);
    const int tid = threadIdx.x;
    const int lane = tid & 31;

    if (tid < 32) {
        for (int e = lane; e < 512; e += 32) sD[e >> 5][e & 31] = gD[e];
        for (int e = lane; e < 256; e += 32) sE[e >> 4][e & 15] = gJ[ts * 256 + e];
        for (int e = lane; e < 256; e += 32) sA[e >> 4][e & 15] = gA[e];
        for (int e = lane; e < 512; e += 32) sCA[e >> 4][e & 15] = gCA[e];
        for (int e = lane; e < 256; e += 32) sCB[e >> 3][e & 7] = gCB[e];
        __syncwarp();
        warp_inv16(sE, lane);
#pragma unroll
        for (int r = 0; r < 16; r++) {
            float s = 0.f;
#pragma unroll
            for (int m = 0; m < 16; m++) s += sE[r][m] * sD[m][lane];
            sK[r][lane] = s;
        }
    } else {
        // stage a[:, t, :] tile: coalesced reads, padded smem (stride 33)
        for (int e = tid - 32; e < 256 * 32; e += 224) {
            int b = e >> 5, c = e & 31;
            sa[b * 33 + c] = a[((size_t)b * TT + t) * 32 + c];
        }
    }
    __syncthreads();

    // M (256 elems) and W (128 elems) computed by all threads
    {
        int i = tid & 15, jj = tid >> 4;   // tid = jj*16 + i
        float s = sA[i][jj];
#pragma unroll
        for (int l = 0; l < 32; l++) s -= sK[i][l] * sCA[l][jj];
        gMT[t * 256 + tid] = s;            // gMT[t][jj][i] = M[i][jj]
    }
    if (tid < 128) {
        int i = tid >> 3, jw = tid & 7;
        float s = Bmat[i * 8 + jw];
#pragma unroll
        for (int l = 0; l < 32; l++) s -= sK[i][l] * sCB[l][jw];
        sW[i][jw] = s;
    }
    __syncthreads();

    // v_{b,t}: thread = b
    {
        const int b = tid;
        const float4* up = reinterpret_cast<const float4*>(u + ((size_t)b * TT + t) * 8);
        float4 u0 = up[0], u1 = up[1];
        float uu[8] = {u0.x, u0.y, u0.z, u0.w, u1.x, u1.y, u1.z, u1.w};
        float aa[32];
#pragma unroll
        for (int c = 0; c < 32; c++) aa[c] = sa[b * 33 + c];
        float v[16];
#pragma unroll
        for (int i = 0; i < 16; i++) {
            float s = 0.f;
#pragma unroll
            for (int k = 0; k < 8; k++) s += sW[i][k] * uu[k];
#pragma unroll
            for (int l = 0; l < 32; l++) s += sK[i][l] * aa[l];
            v[i] = s;
        }
        float4* vp = reinterpret_cast<float4*>(gV + ((size_t)t * BB + b) * 16);
#pragma unroll
        for (int q = 0; q < 4; q++)
            vp[q] = make_float4(v[4 * q], v[4 * q + 1], v[4 * q + 2], v[4 * q + 3]);
    }
}

// ---------------------------------------------------------------------------
// Kernel 2: mean recurrence.  mean_t = M_t mean_{t-1} + v_{b,t}
// 32 blocks x 8 warps; warp = one batch; M^T chunks + v staged in shared.
// ---------------------------------------------------------------------------
__global__ void __launch_bounds__(256) means_kernel(const float* __restrict__ mean0,
                                                    float* __restrict__ out) {
    __shared__ float sMT[CH * 256];      // 16 KB
    __shared__ float sV[8 * CH * 16];    // 8 KB
    const unsigned FULL = 0xffffffffu;
    const int w = threadIdx.x >> 5;
    const int lane = threadIdx.x & 31;
    const int i = lane & 15;
    const int b = blockIdx.x * 8 + w;

    float mean = mean0[b * 16 + i];
    float* ob = out + (size_t)b * TT * 16;

    for (int c = 0; c < TT / CH; c++) {
        __syncthreads();
        for (int e = threadIdx.x; e < CH * 256; e += 256)
            sMT[e] = gMT[c * (CH * 256) + e];
        for (int e = threadIdx.x; e < 8 * CH * 16; e += 256) {
            int wb = e >> 8;           // CH*16 == 256
            int rem = e & 255;
            int tt = rem >> 4, ii = rem & 15;
            sV[e] = gV[((size_t)(c * CH + tt) * BB + (blockIdx.x * 8 + wb)) * 16 + ii];
        }
        __syncthreads();

#pragma unroll 4
        for (int tt = 0; tt < CH; tt++) {
            float acc = sV[(w * CH + tt) * 16 + i];
            const float* Mp = &sMT[tt * 256];
#pragma unroll
            for (int k = 0; k < 16; k++)
                acc += Mp[k * 16 + i] * __shfl_sync(FULL, mean, k, 16);
            mean = acc;
            if (lane < 16) ob[(c * CH + tt) * 16 + i] = acc;
        }
    }
}

// ---------------------------------------------------------------------------
extern "C" void kernel_launch(void* const* d_in, const int* in_sizes, int n_in,
                              void* d_out, int out_size) {
    const float* mean0 = (const float*)d_in[0];
    const float* cov0  = (const float*)d_in[1];
    const float* u     = (const float*)d_in[2];
    const float* a     = (const float*)d_in[3];
    const float* Mmat  = (const float*)d_in[4];
    const float* Nmat  = (const float*)d_in[5];
    const float* dvec  = (const float*)d_in[6];
    const float* Bmat  = (const float*)d_in[7];
    const float* Cmat  = (const float*)d_in[8];
    const float* nx    = (const float*)d_in[9];
    const float* na    = (const float*)d_in[10];
    float* out = (float*)d_out;

    prep_riccati_kernel<<<1, 32>>>(Mmat, Nmat, dvec, Bmat, Cmat, nx, na, cov0);
    gainsv_kernel<<<TT, 256>>>(Bmat, u, a);
    means_kernel<<<BB / 8, 256>>>(mean0, out);
}

// round 5
// speedup vs baseline: 14.0729x; 2.0760x over previous
#include <cuda_runtime.h>
#include <math.h>

#define XD 16
#define UD 8
#define AD 32
#define TT 256
#define BB 256
#define T0 24          // Riccati steps computed exactly; converged afterwards
#define NGJ 4          // exact Gauss-Jordan steps before Newton-Schulz takes over
#define CH 16          // time-chunk for means kernel

// Persistent scratch (device globals — no runtime allocation)
__device__ float gA[XD * XD];
__device__ float gD[XD * AD];
__device__ float gCA[AD * XD];
__device__ float gCB[AD * UD];
__device__ float gJ[T0 * XD * XD];         // posterior information matrices
__device__ float gMT[TT * XD * XD];        // M_t^T : gMT[t][j][i] = M_t[i][j]
__device__ float gV[(size_t)TT * BB * XD]; // v layout [t][b][16]

__device__ __forceinline__ float softplusf(float x) {
    if (x > 20.f) return x;
    return log1pf(expf(x));
}

__device__ __forceinline__ float frcp(float x) {
    float r;
    asm("rcp.approx.ftz.f32 %0, %1;" : "=f"(r) : "f"(x));
    return r;
}

// ---------------------------------------------------------------------------
// In-register Gauss-Jordan inverse of 16x16 SPD, one warp.
// Layout: lane = j + 16*h owns column j, rows h*8 .. h*8+7 (E[m]).
// ---------------------------------------------------------------------------
__device__ __forceinline__ void reg_inv16(float E[8], int j, int h) {
    const unsigned FULL = 0xffffffffu;
#pragma unroll
    for (int k = 0; k < 16; k++) {
        const int hk = k >> 3;
        const int rk = k & 7;
        float piv = __shfl_sync(FULL, E[rk], k + (hk << 4));
        float p = frcp(piv);
        float rowk = __shfl_sync(FULL, E[rk], j + (hk << 4));
        float colk[8];
#pragma unroll
        for (int m = 0; m < 8; m++) colk[m] = __shfl_sync(FULL, E[m], k + (h << 4));
        float pr = p * rowk;
#pragma unroll
        for (int m = 0; m < 8; m++) {
            int i = (h << 3) + m;
            float En = E[m] - colk[m] * pr;
            if (i == k) En = (j == k) ? p : pr;
            else if (j == k) En = -colk[m] * p;
            E[m] = En;
        }
    }
}

// ---------------------------------------------------------------------------
// Shared-memory Gauss-Jordan inverse of 16x16 SPD (one warp) — used in the
// PARALLEL gains kernel where latency is hidden across blocks.
// ---------------------------------------------------------------------------
__device__ __forceinline__ void warp_inv16(float (*E)[17], int lane) {
    const int j = lane & 15, h = lane >> 4;
    for (int k = 0; k < 16; k++) {
        float p = 1.0f / E[k][k];
        float rowk = E[k][j];
        float colk[8];
#pragma unroll
        for (int m = 0; m < 8; m++) colk[m] = E[2 * m + h][k];
        __syncwarp();
#pragma unroll
        for (int m = 0; m < 8; m++) {
            int i = 2 * m + h;
            float val;
            if (i == k) {
                val = (j == k) ? p : rowk * p;
            } else if (j == k) {
                val = -colk[m] * p;
            } else {
                val = E[i][j] - colk[m] * (p * rowk);
            }
            E[i][j] = val;
        }
        __syncwarp();
    }
}

// ---------------------------------------------------------------------------
// Register-column MGS QR. Lane l holds column (l&15) of X in x[16]; writes Q
// to Qs. Positive-diagonal R convention (MGS norms > 0) matches reference.
// ---------------------------------------------------------------------------
__device__ __forceinline__ void warp_qr_reg(float x[16], float (*Qs)[17], int lane) {
    const unsigned FULL = 0xffffffffu;
    const int j = lane & 15;
#pragma unroll
    for (int k = 0; k < 16; k++) {
        float qk[16];
#pragma unroll
        for (int i = 0; i < 16; i++) qk[i] = __shfl_sync(FULL, x[i], k);
        float nrm = 0.f;
#pragma unroll
        for (int i = 0; i < 16; i++) nrm += qk[i] * qk[i];
        float inv = rsqrtf(nrm);
#pragma unroll
        for (int i = 0; i < 16; i++) qk[i] *= inv;
        if (lane == k) {
#pragma unroll
            for (int i = 0; i < 16; i++) Qs[i][k] = qk[i];
        }
        float dot = 0.f;
#pragma unroll
        for (int i = 0; i < 16; i++) dot += qk[i] * x[i];
        if (j > k) {
#pragma unroll
            for (int i = 0; i < 16; i++) x[i] -= dot * qk[i];
        }
    }
}

// ---------------------------------------------------------------------------
// Kernel 0: prep (constants) + sequential Riccati, one warp, one launch.
// ---------------------------------------------------------------------------
__global__ void __launch_bounds__(32) prep_riccati_kernel(
    const float* __restrict__ Mmat, const float* __restrict__ Nmat,
    const float* __restrict__ dvec, const float* __restrict__ Bmat,
    const float* __restrict__ Cmat,
    const float* __restrict__ nx, const float* __restrict__ na,
    const float* __restrict__ cov0) {
    __shared__ float sQ[16][17], sU[16][17], sA[16][17], sW[16][17];
    __shared__ float sZ[16][17], sR0[16][17], sG[16][17];
    __shared__ float sE[16][17], sF[16][17], sT[16][17];
    __shared__ float s1[16], s2[16], nxis[16], nais[32];
    const unsigned FULL = 0xffffffffu;
    const int lane = threadIdx.x;
    const int j = lane & 15, h = lane >> 4;

    // ---------- QR factors (register-column MGS) ----------
    {
        float x[16];
#pragma unroll
        for (int i = 0; i < 16; i++) x[i] = Mmat[i * 16 + j];
        warp_qr_reg(x, sQ, lane);
#pragma unroll
        for (int i = 0; i < 16; i++) x[i] = Nmat[i * 16 + j];
        warp_qr_reg(x, sU, lane);
    }

    if (lane < 16) {
        float dsp = softplusf(dvec[lane]);
        s1[lane] = sqrtf(dsp);
        s2[lane] = 1.0f / sqrtf(1.0f + dsp);
        nxis[lane] = 1.0f / (softplusf(nx[lane]) + 1e-4f);
    }
    nais[lane] = 1.0f / (softplusf(na[lane]) + 1e-4f);
    __syncwarp();

    // ---------- A = Uq diag(s1) Q diag(s2) Uq^T ----------
#pragma unroll
    for (int m = 0; m < 8; m++) {
        int i = 2 * m + h;
        float s = 0.f;
#pragma unroll
        for (int k = 0; k < 16; k++) s += sU[i][k] * s1[k] * sQ[k][j];
        sW[i][j] = s;
    }
    __syncwarp();
    {
        float Ur[16];
#pragma unroll
        for (int k = 0; k < 16; k++) Ur[k] = sU[j][k] * s2[k];
#pragma unroll
        for (int m = 0; m < 8; m++) {
            int i = 2 * m + h;
            float s = 0.f;
#pragma unroll
            for (int k = 0; k < 16; k++) s += sW[i][k] * Ur[k];
            sA[i][j] = s;
            gA[i * 16 + j] = s;
        }
    }
    __syncwarp();

    // ---------- Z, R0, G, D, CA, CB ----------
#pragma unroll
    for (int m = 0; m < 8; m++) {
        int i = 2 * m + h;
        sZ[i][j] = nxis[i] * sA[i][j];
    }
    __syncwarp();
#pragma unroll
    for (int m = 0; m < 8; m++) {
        int i = 2 * m + h;
        float s = 0.f;
#pragma unroll
        for (int k = 0; k < 16; k++) s += sA[k][i] * nxis[k] * sA[k][j];
        sR0[i][j] = s;
    }
#pragma unroll
    for (int m = 0; m < 8; m++) {
        int i = 2 * m + h;
        float s = 0.f;
#pragma unroll
        for (int k = 0; k < 32; k++) s += Cmat[k * 16 + i] * nais[k] * Cmat[k * 16 + j];
        sG[i][j] = s;
    }
    for (int e = lane; e < 512; e += 32) {
        int i = e >> 5, c = e & 31;
        gD[i * 32 + c] = Cmat[c * 16 + i] * nais[c];
    }
    {
        float Crow[16];
#pragma unroll
        for (int k = 0; k < 16; k++) Crow[k] = Cmat[lane * 16 + k];
#pragma unroll
        for (int jj = 0; jj < 16; jj++) {
            float s = 0.f;
#pragma unroll
            for (int k = 0; k < 16; k++) s += Crow[k] * sA[k][jj];
            gCA[lane * 16 + jj] = s;
        }
#pragma unroll
        for (int jj = 0; jj < 8; jj++) {
            float s = 0.f;
#pragma unroll
            for (int k = 0; k < 16; k++) s += Crow[k] * Bmat[k * 8 + jj];
            gCB[lane * 8 + jj] = s;
        }
    }
    __syncwarp();

    // ---------- Riccati (layout: lane = j + 16*h owns col j, rows h*8..h*8+7) ----------
    float Rc[8], Gc[8], Jr[8], Zr[16];
#pragma unroll
    for (int m = 0; m < 8; m++) {
        int i = (h << 3) + m;
        Rc[m] = sR0[i][j];
        Gc[m] = sG[i][j];
        Jr[m] = cov0[i * 16 + j];   // will be inverted in-place
    }
#pragma unroll
    for (int k = 0; k < 16; k++) Zr[k] = sZ[j][k];
    float nxij = nxis[j];
    __syncwarp();

    // J0 = inv(cov0[0]) — register GJ
    reg_inv16(Jr, j, h);

    for (int t = 0; t < T0; t++) {
        if (t < NGJ) {
            // exact inverse via register GJ
            float E[8];
#pragma unroll
            for (int m = 0; m < 8; m++) E[m] = Jr[m] + Rc[m];
            reg_inv16(E, j, h);
#pragma unroll
            for (int m = 0; m < 8; m++) sF[(h << 3) + m][j] = E[m];
            __syncwarp();
        } else {
            // Newton-Schulz with warm start (sF from previous step), 3 iters
#pragma unroll
            for (int m = 0; m < 8; m++) sE[(h << 3) + m][j] = Jr[m] + Rc[m];
            __syncwarp();
#pragma unroll
            for (int it = 0; it < 3; it++) {
                float Fc[16];
#pragma unroll
                for (int k = 0; k < 16; k++) Fc[k] = sF[k][j];
                float Rr[8];
#pragma unroll
                for (int m = 0; m < 8; m++) {
                    int i = (h << 3) + m;
                    float s = (i == j) ? 2.0f : 0.0f;
#pragma unroll
                    for (int k = 0; k < 16; k++) s -= sE[i][k] * Fc[k];
                    Rr[m] = s;
                }
                __syncwarp();
#pragma unroll
                for (int m = 0; m < 8; m++) sT[(h << 3) + m][j] = Rr[m];
                __syncwarp();
                float Tc[16];
#pragma unroll
                for (int k = 0; k < 16; k++) Tc[k] = sT[k][j];
                float Fn[8];
#pragma unroll
                for (int m = 0; m < 8; m++) {
                    int i = (h << 3) + m;
                    float s = 0.f;
#pragma unroll
                    for (int k = 0; k < 16; k++) s += sF[i][k] * Tc[k];
                    Fn[m] = s;
                }
                __syncwarp();
#pragma unroll
                for (int m = 0; m < 8; m++) sF[(h << 3) + m][j] = Fn[m];
                __syncwarp();
            }
        }

        // common tail: T = Z*F ; Jm = diag(nxi) - T*Z^T ; J = Jm + G (stored)
        float Fc[16];
#pragma unroll
        for (int k = 0; k < 16; k++) Fc[k] = sF[k][j];
        float Tr[8];
#pragma unroll
        for (int m = 0; m < 8; m++) {
            int i = (h << 3) + m;
            float s = 0.f;
#pragma unroll
            for (int k = 0; k < 16; k++) s += sZ[i][k] * Fc[k];
            Tr[m] = s;
        }
        __syncwarp();
#pragma unroll
        for (int m = 0; m < 8; m++) sT[(h << 3) + m][j] = Tr[m];
        __syncwarp();
        float* gj = gJ + t * 256;
#pragma unroll
        for (int m = 0; m < 8; m++) {
            int i = (h << 3) + m;
            float s = (i == j) ? nxij : 0.f;
#pragma unroll
            for (int k = 0; k < 16; k++) s -= sT[i][k] * Zr[k];
            float jn = s + Gc[m];
            gj[i * 16 + j] = jn;
            Jr[m] = jn;
        }
        __syncwarp();
    }
}

// ---------------------------------------------------------------------------
// Kernel 1: per-t (256 blocks x 256 threads), fused gains + v.
//   warp0: P+ = gJ[min(t,T0-1)]^{-1}, K = P+ D   (warps 1-7 stage a-tile)
//   all:   M_t = A - K CA (-> gMT, transposed), W_t = B - K CB
//   all:   v_{b,t} = W_t u + K a   (thread = b), gV layout [t][b][16]
// ---------------------------------------------------------------------------
__global__ void __launch_bounds__(256) gainsv_kernel(const float* __restrict__ Bmat,
                                                     const float* __restrict__ u,
                                                     const float* __restrict__ a) {
    __shared__ float sE[16][17], sD[16][33], sK[16][33], sA[16][17];
    __shared__ float sCA[32][17], sCB[32][9], sW[16][9];
    __shared__ float sa[256 * 33];
    const int t = blockIdx.x;
    const int ts = (t < T0) ? t : (T0 - 1);
    const int tid = threadIdx.x;
    const int lane = tid & 31;

    if (tid < 32) {
        for (int e = lane; e < 512; e += 32) sD[e >> 5][e & 31] = gD[e];
        for (int e = lane; e < 256; e += 32) sE[e >> 4][e & 15] = gJ[ts * 256 + e];
        for (int e = lane; e < 256; e += 32) sA[e >> 4][e & 15] = gA[e];
        for (int e = lane; e < 512; e += 32) sCA[e >> 4][e & 15] = gCA[e];
        for (int e = lane; e < 256; e += 32) sCB[e >> 3][e & 7] = gCB[e];
        __syncwarp();
        warp_inv16(sE, lane);
#pragma unroll
        for (int r = 0; r < 16; r++) {
            float s = 0.f;
#pragma unroll
            for (int m = 0; m < 16; m++) s += sE[r][m] * sD[m][lane];
            sK[r][lane] = s;
        }
    } else {
        // stage a[:, t, :] tile: coalesced reads, padded smem (stride 33)
        for (int e = tid - 32; e < 256 * 32; e += 224) {
            int b = e >> 5, c = e & 31;
            sa[b * 33 + c] = a[((size_t)b * TT + t) * 32 + c];
        }
    }
    __syncthreads();

    // M (256 elems) and W (128 elems) computed by all threads
    {
        int i = tid & 15, jj = tid >> 4;   // tid = jj*16 + i
        float s = sA[i][jj];
#pragma unroll
        for (int l = 0; l < 32; l++) s -= sK[i][l] * sCA[l][jj];
        gMT[t * 256 + tid] = s;            // gMT[t][jj][i] = M[i][jj]
    }
    if (tid < 128) {
        int i = tid >> 3, jw = tid & 7;
        float s = Bmat[i * 8 + jw];
#pragma unroll
        for (int l = 0; l < 32; l++) s -= sK[i][l] * sCB[l][jw];
        sW[i][jw] = s;
    }
    __syncthreads();

    // v_{b,t}: thread = b
    {
        const int b = tid;
        const float4* up = reinterpret_cast<const float4*>(u + ((size_t)b * TT + t) * 8);
        float4 u0 = up[0], u1 = up[1];
        float uu[8] = {u0.x, u0.y, u0.z, u0.w, u1.x, u1.y, u1.z, u1.w};
        float aa[32];
#pragma unroll
        for (int c = 0; c < 32; c++) aa[c] = sa[b * 33 + c];
        float v[16];
#pragma unroll
        for (int i = 0; i < 16; i++) {
            float s = 0.f;
#pragma unroll
            for (int k = 0; k < 8; k++) s += sW[i][k] * uu[k];
#pragma unroll
            for (int l = 0; l < 32; l++) s += sK[i][l] * aa[l];
            v[i] = s;
        }
        float4* vp = reinterpret_cast<float4*>(gV + ((size_t)t * BB + b) * 16);
#pragma unroll
        for (int q = 0; q < 4; q++)
            vp[q] = make_float4(v[4 * q], v[4 * q + 1], v[4 * q + 2], v[4 * q + 3]);
    }
}

// ---------------------------------------------------------------------------
// Kernel 2: mean recurrence.  mean_t = M_t mean_{t-1} + v_{b,t}
// 32 blocks x 8 warps; warp = one batch; M^T chunks + v staged in shared.
// ---------------------------------------------------------------------------
__global__ void __launch_bounds__(256) means_kernel(const float* __restrict__ mean0,
                                                    float* __restrict__ out) {
    __shared__ float sMT[CH * 256];      // 16 KB
    __shared__ float sV[8 * CH * 16];    // 8 KB
    const unsigned FULL = 0xffffffffu;
    const int w = threadIdx.x >> 5;
    const int lane = threadIdx.x & 31;
    const int i = lane & 15;
    const int b = blockIdx.x * 8 + w;

    float mean = mean0[b * 16 + i];
    float* ob = out + (size_t)b * TT * 16;

    for (int c = 0; c < TT / CH; c++) {
        __syncthreads();
        for (int e = threadIdx.x; e < CH * 256; e += 256)
            sMT[e] = gMT[c * (CH * 256) + e];
        for (int e = threadIdx.x; e < 8 * CH * 16; e += 256) {
            int wb = e >> 8;           // CH*16 == 256
            int rem = e & 255;
            int tt = rem >> 4, ii = rem & 15;
            sV[e] = gV[((size_t)(c * CH + tt) * BB + (blockIdx.x * 8 + wb)) * 16 + ii];
        }
        __syncthreads();

#pragma unroll 4
        for (int tt = 0; tt < CH; tt++) {
            float acc = sV[(w * CH + tt) * 16 + i];
            const float* Mp = &sMT[tt * 256];
#pragma unroll
            for (int k = 0; k < 16; k++)
                acc += Mp[k * 16 + i] * __shfl_sync(FULL, mean, k, 16);
            mean = acc;
            if (lane < 16) ob[(c * CH + tt) * 16 + i] = acc;
        }
    }
}

// ---------------------------------------------------------------------------
extern "C" void kernel_launch(void* const* d_in, const int* in_sizes, int n_in,
                              void* d_out, int out_size) {
    const float* mean0 = (const float*)d_in[0];
    const float* cov0  = (const float*)d_in[1];
    const float* u     = (const float*)d_in[2];
    const float* a     = (const float*)d_in[3];
    const float* Mmat  = (const float*)d_in[4];
    const float* Nmat  = (const float*)d_in[5];
    const float* dvec  = (const float*)d_in[6];
    const float* Bmat  = (const float*)d_in[7];
    const float* Cmat  = (const float*)d_in[8];
    const float* nx    = (const float*)d_in[9];
    const float* na    = (const float*)d_in[10];
    float* out = (float*)d_out;

    prep_riccati_kernel<<<1, 32>>>(Mmat, Nmat, dvec, Bmat, Cmat, nx, na, cov0);
    gainsv_kernel<<<TT, 256>>>(Bmat, u, a);
    means_kernel<<<BB / 8, 256>>>(mean0, out);
}

// round 7
// speedup vs baseline: 15.5385x; 1.1041x over previous
#include <cuda_runtime.h>
#include <math.h>

#define XD 16
#define UD 8
#define AD 32
#define TT 256
#define BB 256
#define T0 16          // Riccati steps computed exactly; converged afterwards
#define CH 16          // time-chunk for means kernel

// Persistent scratch (device globals — no runtime allocation)
__device__ float gA[XD * XD];
__device__ float gD[XD * AD];
__device__ float gCA[AD * XD];
__device__ float gCB[AD * UD];
__device__ float gJ[T0 * XD * XD];         // posterior information matrices
__device__ float gMT[TT * XD * XD];        // M_t^T : gMT[t][j][i] = M_t[i][j]
__device__ float gV[(size_t)TT * BB * XD]; // v layout [t][b][16]

__device__ __forceinline__ float softplusf(float x) {
    if (x > 20.f) return x;
    return log1pf(expf(x));
}

__device__ __forceinline__ float frcp(float x) {
    float r;
    asm("rcp.approx.ftz.f32 %0, %1;" : "=f"(r) : "f"(x));
    return r;
}

// ---------------------------------------------------------------------------
// In-register Gauss-Jordan inverse of 16x16 SPD, one warp.
// Layout: lane = j + 16*h owns column j, rows h*8 .. h*8+7 (E[m]).
// ---------------------------------------------------------------------------
__device__ __forceinline__ void reg_inv16(float E[8], int j, int h) {
    const unsigned FULL = 0xffffffffu;
#pragma unroll
    for (int k = 0; k < 16; k++) {
        const int hk = k >> 3;
        const int rk = k & 7;
        float piv = __shfl_sync(FULL, E[rk], k + (hk << 4));
        float p = frcp(piv);
        float rowk = __shfl_sync(FULL, E[rk], j + (hk << 4));
        float colk[8];
#pragma unroll
        for (int m = 0; m < 8; m++) colk[m] = __shfl_sync(FULL, E[m], k + (h << 4));
        float pr = p * rowk;
#pragma unroll
        for (int m = 0; m < 8; m++) {
            int i = (h << 3) + m;
            float En = E[m] - colk[m] * pr;
            if (i == k) En = (j == k) ? p : pr;
            else if (j == k) En = -colk[m] * p;
            E[m] = En;
        }
    }
}

// ---------------------------------------------------------------------------
// Shared-memory Gauss-Jordan inverse of 16x16 SPD (one warp) — used in the
// PARALLEL gains kernel where latency is hidden across blocks.
// ---------------------------------------------------------------------------
__device__ __forceinline__ void warp_inv16(float (*E)[17], int lane) {
    const int j = lane & 15, h = lane >> 4;
    for (int k = 0; k < 16; k++) {
        float p = 1.0f / E[k][k];
        float rowk = E[k][j];
        float colk[8];
#pragma unroll
        for (int m = 0; m < 8; m++) colk[m] = E[2 * m + h][k];
        __syncwarp();
#pragma unroll
        for (int m = 0; m < 8; m++) {
            int i = 2 * m + h;
            float val;
            if (i == k) {
                val = (j == k) ? p : rowk * p;
            } else if (j == k) {
                val = -colk[m] * p;
            } else {
                val = E[i][j] - colk[m] * (p * rowk);
            }
            E[i][j] = val;
        }
        __syncwarp();
    }
}

// ---------------------------------------------------------------------------
// Register-column MGS QR. Lane l holds column (l&15) of X in x[16]; writes Q
// to Qs. Positive-diagonal R convention (MGS norms > 0) matches reference.
// ---------------------------------------------------------------------------
__device__ __forceinline__ void warp_qr_reg(float x[16], float (*Qs)[17], int lane) {
    const unsigned FULL = 0xffffffffu;
    const int j = lane & 15;
#pragma unroll
    for (int k = 0; k < 16; k++) {
        float qk[16];
#pragma unroll
        for (int i = 0; i < 16; i++) qk[i] = __shfl_sync(FULL, x[i], k);
        float nrm = 0.f;
#pragma unroll
        for (int i = 0; i < 16; i++) nrm += qk[i] * qk[i];
        float inv = rsqrtf(nrm);
#pragma unroll
        for (int i = 0; i < 16; i++) qk[i] *= inv;
        if (lane == k) {
#pragma unroll
            for (int i = 0; i < 16; i++) Qs[i][k] = qk[i];
        }
        float dot = 0.f;
#pragma unroll
        for (int i = 0; i < 16; i++) dot += qk[i] * x[i];
        if (j > k) {
#pragma unroll
            for (int i = 0; i < 16; i++) x[i] -= dot * qk[i];
        }
    }
}

// ---------------------------------------------------------------------------
// Kernel 0: prep (constants) + sequential Riccati, one warp, one launch.
// ---------------------------------------------------------------------------
__global__ void __launch_bounds__(32) prep_riccati_kernel(
    const float* __restrict__ Mmat, const float* __restrict__ Nmat,
    const float* __restrict__ dvec, const float* __restrict__ Bmat,
    const float* __restrict__ Cmat,
    const float* __restrict__ nx, const float* __restrict__ na,
    const float* __restrict__ cov0) {
    __shared__ float sQ[16][17], sU[16][17], sA[16][17], sW[16][17];
    __shared__ float sZ[16][17], sT[16][17];
    __shared__ float s1[16], s2[16], nxis[16], nais[32];
    const unsigned FULL = 0xffffffffu;
    const int lane = threadIdx.x;
    const int j = lane & 15, h = lane >> 4;

    // ---------- QR factors (register-column MGS) ----------
    {
        float x[16];
#pragma unroll
        for (int i = 0; i < 16; i++) x[i] = Mmat[i * 16 + j];
        warp_qr_reg(x, sQ, lane);
#pragma unroll
        for (int i = 0; i < 16; i++) x[i] = Nmat[i * 16 + j];
        warp_qr_reg(x, sU, lane);
    }

    if (lane < 16) {
        float dsp = softplusf(dvec[lane]);
        s1[lane] = sqrtf(dsp);
        s2[lane] = 1.0f / sqrtf(1.0f + dsp);
        nxis[lane] = 1.0f / (softplusf(nx[lane]) + 1e-4f);
    }
    nais[lane] = 1.0f / (softplusf(na[lane]) + 1e-4f);
    __syncwarp();

    // ---------- A = Uq diag(s1) Q diag(s2) Uq^T ----------
#pragma unroll
    for (int m = 0; m < 8; m++) {
        int i = 2 * m + h;
        float s = 0.f;
#pragma unroll
        for (int k = 0; k < 16; k++) s += sU[i][k] * s1[k] * sQ[k][j];
        sW[i][j] = s;
    }
    __syncwarp();
    {
        float Ur[16];
#pragma unroll
        for (int k = 0; k < 16; k++) Ur[k] = sU[j][k] * s2[k];
#pragma unroll
        for (int m = 0; m < 8; m++) {
            int i = 2 * m + h;
            float s = 0.f;
#pragma unroll
            for (int k = 0; k < 16; k++) s += sW[i][k] * Ur[k];
            sA[i][j] = s;
            gA[i * 16 + j] = s;
        }
    }
    __syncwarp();

    // ---------- Z, R0, G, D, CA, CB ----------
    float Rc[8], Gc[8], Jr[8], Zr[16];
#pragma unroll
    for (int m = 0; m < 8; m++) {
        int i = 2 * m + h;
        sZ[i][j] = nxis[i] * sA[i][j];
    }
    __syncwarp();
    // riccati layout is lane = j + 16*h owning rows (h*8+m); compute Rc/Gc directly
#pragma unroll
    for (int m = 0; m < 8; m++) {
        int i = (h << 3) + m;
        float s = 0.f;
#pragma unroll
        for (int k = 0; k < 16; k++) s += sA[k][i] * nxis[k] * sA[k][j];
        Rc[m] = s;
    }
#pragma unroll
    for (int m = 0; m < 8; m++) {
        int i = (h << 3) + m;
        float s = 0.f;
#pragma unroll
        for (int k = 0; k < 32; k++) s += Cmat[k * 16 + i] * nais[k] * Cmat[k * 16 + j];
        Gc[m] = s;
    }
    for (int e = lane; e < 512; e += 32) {
        int i = e >> 5, c = e & 31;
        gD[i * 32 + c] = Cmat[c * 16 + i] * nais[c];
    }
    {
        float Crow[16];
#pragma unroll
        for (int k = 0; k < 16; k++) Crow[k] = Cmat[lane * 16 + k];
#pragma unroll
        for (int jj = 0; jj < 16; jj++) {
            float s = 0.f;
#pragma unroll
            for (int k = 0; k < 16; k++) s += Crow[k] * sA[k][jj];
            gCA[lane * 16 + jj] = s;
        }
#pragma unroll
        for (int jj = 0; jj < 8; jj++) {
            float s = 0.f;
#pragma unroll
            for (int k = 0; k < 16; k++) s += Crow[k] * Bmat[k * 8 + jj];
            gCB[lane * 8 + jj] = s;
        }
    }
#pragma unroll
    for (int k = 0; k < 16; k++) Zr[k] = sZ[j][k];
    float nxij = nxis[j];

    // J0 = inv(cov0[0]) — register GJ (riccati layout)
#pragma unroll
    for (int m = 0; m < 8; m++) Jr[m] = cov0[((h << 3) + m) * 16 + j];
    reg_inv16(Jr, j, h);
    __syncwarp();

    // ---------- Riccati: E=J+R0 ; F=E^-1 (reg GJ) ; Jm=diag(nxi)-Z F Z^T ; J=Jm+G ----------
    for (int t = 0; t < T0; t++) {
        float E[8];
#pragma unroll
        for (int m = 0; m < 8; m++) E[m] = Jr[m] + Rc[m];
        reg_inv16(E, j, h);

        // full column j of F
        float Fc[16];
#pragma unroll
        for (int m = 0; m < 8; m++) {
            Fc[(h << 3) + m] = E[m];
            Fc[((1 - h) << 3) + m] = __shfl_xor_sync(FULL, E[m], 16);
        }

        // T[:,j]: T[i][j] = sum_k Z[i][k] F[k][j]  -> store to shared
#pragma unroll
        for (int m = 0; m < 8; m++) {
            int i = (h << 3) + m;
            float s0 = 0.f, s1a = 0.f;
#pragma unroll
            for (int k = 0; k < 8; k++) {
                s0 += sZ[i][2 * k] * Fc[2 * k];
                s1a += sZ[i][2 * k + 1] * Fc[2 * k + 1];
            }
            sT[i][j] = s0 + s1a;
        }
        __syncwarp();

        // Jm[i][j] = nxi_ij - sum_k T[i][k] Z[j][k] ; J = Jm + G (stored)
        float* gj = gJ + t * 256;
#pragma unroll
        for (int m = 0; m < 8; m++) {
            int i = (h << 3) + m;
            float s0 = (i == j) ? nxij : 0.f, s1a = 0.f;
#pragma unroll
            for (int k = 0; k < 8; k++) {
                s0 -= sT[i][2 * k] * Zr[2 * k];
                s1a -= sT[i][2 * k + 1] * Zr[2 * k + 1];
            }
            float jn = s0 + s1a + Gc[m];   // FIXED: was s0 - s1a (sign bug)
            gj[i * 16 + j] = jn;
            Jr[m] = jn;
        }
        __syncwarp();
    }
}

// ---------------------------------------------------------------------------
// Kernel 1: per-t (256 blocks x 256 threads), fused gains + v.
//   warp0: P+ = gJ[min(t,T0-1)]^{-1}, K = P+ D   (warps 1-7 stage a-tile)
//   all:   M_t = A - K CA (-> gMT, transposed), W_t = B - K CB
//   all:   v_{b,t} = W_t u + K a   (thread = b), gV layout [t][b][16]
// ---------------------------------------------------------------------------
__global__ void __launch_bounds__(256) gainsv_kernel(const float* __restrict__ Bmat,
                                                     const float* __restrict__ u,
                                                     const float* __restrict__ a) {
    __shared__ float sE[16][17], sD[16][33], sK[16][33], sA[16][17];
    __shared__ float sCA[32][17], sCB[32][9], sW[16][9];
    __shared__ float sa[256 * 33];
    const int t = blockIdx.x;
    const int ts = (t < T0) ? t : (T0 - 1);
    const int tid = threadIdx.x;
    const int lane = tid & 31;

    if (tid < 32) {
        for (int e = lane; e < 512; e += 32) sD[e >> 5][e & 31] = gD[e];
        for (int e = lane; e < 256; e += 32) sE[e >> 4][e & 15] = gJ[ts * 256 + e];
        for (int e = lane; e < 256; e += 32) sA[e >> 4][e & 15] = gA[e];
        for (int e = lane; e < 512; e += 32) sCA[e >> 4][e & 15] = gCA[e];
        for (int e = lane; e < 256; e += 32) sCB[e >> 3][e & 7] = gCB[e];
        __syncwarp();
        warp_inv16(sE, lane);
#pragma unroll
        for (int r = 0; r < 16; r++) {
            float s = 0.f;
#pragma unroll
            for (int m = 0; m < 16; m++) s += sE[r][m] * sD[m][lane];
            sK[r][lane] = s;
        }
    } else {
        // stage a[:, t, :] tile: coalesced reads, padded smem (stride 33)
        for (int e = tid - 32; e < 256 * 32; e += 224) {
            int b = e >> 5, c = e & 31;
            sa[b * 33 + c] = a[((size_t)b * TT + t) * 32 + c];
        }
    }
    __syncthreads();

    // M (256 elems) and W (128 elems) computed by all threads
    {
        int i = tid & 15, jj = tid >> 4;   // tid = jj*16 + i
        float s = sA[i][jj];
#pragma unroll
        for (int l = 0; l < 32; l++) s -= sK[i][l] * sCA[l][jj];
        gMT[t * 256 + tid] = s;            // gMT[t][jj][i] = M[i][jj]
    }
    if (tid < 128) {
        int i = tid >> 3, jw = tid & 7;
        float s = Bmat[i * 8 + jw];
#pragma unroll
        for (int l = 0; l < 32; l++) s -= sK[i][l] * sCB[l][jw];
        sW[i][jw] = s;
    }
    __syncthreads();

    // v_{b,t}: thread = b
    {
        const int b = tid;
        const float4* up = reinterpret_cast<const float4*>(u + ((size_t)b * TT + t) * 8);
        float4 u0 = up[0], u1 = up[1];
        float uu[8] = {u0.x, u0.y, u0.z, u0.w, u1.x, u1.y, u1.z, u1.w};
        float aa[32];
#pragma unroll
        for (int c = 0; c < 32; c++) aa[c] = sa[b * 33 + c];
        float v[16];
#pragma unroll
        for (int i = 0; i < 16; i++) {
            float s = 0.f;
#pragma unroll
            for (int k = 0; k < 8; k++) s += sW[i][k] * uu[k];
#pragma unroll
            for (int l = 0; l < 32; l++) s += sK[i][l] * aa[l];
            v[i] = s;
        }
        float4* vp = reinterpret_cast<float4*>(gV + ((size_t)t * BB + b) * 16);
#pragma unroll
        for (int q = 0; q < 4; q++)
            vp[q] = make_float4(v[4 * q], v[4 * q + 1], v[4 * q + 2], v[4 * q + 3]);
    }
}

// ---------------------------------------------------------------------------
// Kernel 2: mean recurrence.  mean_t = M_t mean_{t-1} + v_{b,t}
// 32 blocks x 8 warps; warp = one batch; M^T chunks + v staged in shared.
// 4-way split accumulators shorten the serial FMA chain.
// ---------------------------------------------------------------------------
__global__ void __launch_bounds__(256) means_kernel(const float* __restrict__ mean0,
                                                    float* __restrict__ out) {
    __shared__ float sMT[CH * 256];      // 16 KB
    __shared__ float sV[8 * CH * 16];    // 8 KB
    const unsigned FULL = 0xffffffffu;
    const int w = threadIdx.x >> 5;
    const int lane = threadIdx.x & 31;
    const int i = lane & 15;
    const int b = blockIdx.x * 8 + w;

    float mean = mean0[b * 16 + i];
    float* ob = out + (size_t)b * TT * 16;

    for (int c = 0; c < TT / CH; c++) {
        __syncthreads();
        for (int e = threadIdx.x; e < CH * 256; e += 256)
            sMT[e] = gMT[c * (CH * 256) + e];
        for (int e = threadIdx.x; e < 8 * CH * 16; e += 256) {
            int wb = e >> 8;           // CH*16 == 256
            int rem = e & 255;
            int tt = rem >> 4, ii = rem & 15;
            sV[e] = gV[((size_t)(c * CH + tt) * BB + (blockIdx.x * 8 + wb)) * 16 + ii];
        }
        __syncthreads();

#pragma unroll 4
        for (int tt = 0; tt < CH; tt++) {
            const float* Mp = &sMT[tt * 256];
            float a0 = sV[(w * CH + tt) * 16 + i], a1 = 0.f, a2 = 0.f, a3 = 0.f;
#pragma unroll
            for (int k = 0; k < 4; k++) {
                a0 += Mp[(4 * k + 0) * 16 + i] * __shfl_sync(FULL, mean, 4 * k + 0, 16);
                a1 += Mp[(4 * k + 1) * 16 + i] * __shfl_sync(FULL, mean, 4 * k + 1, 16);
                a2 += Mp[(4 * k + 2) * 16 + i] * __shfl_sync(FULL, mean, 4 * k + 2, 16);
                a3 += Mp[(4 * k + 3) * 16 + i] * __shfl_sync(FULL, mean, 4 * k + 3, 16);
            }
            mean = (a0 + a1) + (a2 + a3);
            if (lane < 16) ob[(c * CH + tt) * 16 + i] = mean;
        }
    }
}

// ---------------------------------------------------------------------------
extern "C" void kernel_launch(void* const* d_in, const int* in_sizes, int n_in,
                              void* d_out, int out_size) {
    const float* mean0 = (const float*)d_in[0];
    const float* cov0  = (const float*)d_in[1];
    const float* u     = (const float*)d_in[2];
    const float* a     = (const float*)d_in[3];
    const float* Mmat  = (const float*)d_in[4];
    const float* Nmat  = (const float*)d_in[5];
    const float* dvec  = (const float*)d_in[6];
    const float* Bmat  = (const float*)d_in[7];
    const float* Cmat  = (const float*)d_in[8];
    const float* nx    = (const float*)d_in[9];
    const float* na    = (const float*)d_in[10];
    float* out = (float*)d_out;

    prep_riccati_kernel<<<1, 32>>>(Mmat, Nmat, dvec, Bmat, Cmat, nx, na, cov0);
    gainsv_kernel<<<TT, 256>>>(Bmat, u, a);
    means_kernel<<<BB / 8, 256>>>(mean0, out);
}